// round 7
// baseline (speedup 1.0000x reference)
#include <cuda_runtime.h>
#include <cuda_fp16.h>
#include <cstdint>

#define NN 8192
#define DD 64
// K' = K * 2^KSH stored as e4m3 (64 MB, L2-resident)
#define KSH 10.0f

static __device__ uint8_t g_K[(size_t)NN * NN];
static __device__ float  g_u[NN];
static __device__ float  g_v[NN];
static __device__ float  g_pn[NN];
static __device__ float  g_qn[NN];
static __device__ double g_loss;

__device__ __forceinline__ float fsqrt_ap(float x) { float r; asm("sqrt.approx.f32 %0, %1;" : "=f"(r) : "f"(x)); return r; }
__device__ __forceinline__ float fex2(float x)     { float r; asm("ex2.approx.f32 %0, %1;"  : "=f"(r) : "f"(x)); return r; }
__device__ __forceinline__ float flg2(float x)     { float r; asm("lg2.approx.f32 %0, %1;"  : "=f"(r) : "f"(x)); return r; }

// decode 2 packed e4m3 -> 2 floats (low byte -> .x)
__device__ __forceinline__ float2 dec2(uint32_t p16) {
    uint32_t h2;
    asm("cvt.rn.f16x2.e4m3x2 %0, %1;" : "=r"(h2) : "h"((uint16_t)p16));
    return __half22float2(*(__half2*)&h2);
}
// encode 2 floats -> 2 packed e4m3 (lo -> low byte)
__device__ __forceinline__ uint16_t enc2(float lo, float hi) {
    uint16_t r;
    asm("cvt.rn.satfinite.e4m3x2.f32 %0, %1, %2;" : "=h"(r) : "f"(hi), "f"(lo));
    return r;
}

__global__ void prep_kernel(const float* __restrict__ P, const float* __restrict__ Q) {
    int i = blockIdx.x * blockDim.x + threadIdx.x;
    if (i == 0) g_loss = 0.0;
    if (i < NN) {
        const float4* p = (const float4*)(P + (size_t)i * DD);
        const float4* q = (const float4*)(Q + (size_t)i * DD);
        float sp = 0.f, sq = 0.f;
        #pragma unroll
        for (int k = 0; k < DD / 4; ++k) {
            float4 a = p[k]; sp += a.x*a.x + a.y*a.y + a.z*a.z + a.w*a.w;
            float4 b = q[k]; sq += b.x*b.x + b.y*b.y + b.z*b.z + b.w*b.w;
        }
        g_pn[i] = sp;
        g_qn[i] = sq;
        g_u[i]  = 1.0f / 64.0f;   // reference: ones(N)/D, D=64
    }
}

// K'[i][j] = 2^(KSH - log2(e)/eps * sqrt(max(pn_i+qn_j-2 P_i.Q_j,0))), e4m3 store.
#define LDSW 72
__global__ __launch_bounds__(256) void ck_kernel(const float* __restrict__ P,
                                                 const float* __restrict__ Q) {
    __shared__ __half Ps[128 * LDSW];
    __shared__ __half Qs[128 * LDSW];
    __shared__ float  s_pn[128], s_qn[128];

    const int bi = blockIdx.y * 128, bj = blockIdx.x * 128;
    const int tid = threadIdx.x;
    const int wid = tid >> 5, lane = tid & 31;
    const int g = lane >> 2, tq = lane & 3;
    const int mrow = (wid >> 1) * 32, ncol = (wid & 1) * 64;

    #pragma unroll
    for (int r = 0; r < 8; ++r) {
        int idx = tid + r * 256;
        int row = idx >> 4;
        int c4  = (idx & 15) << 2;
        float4 a = *(const float4*)(P + (size_t)(bi + row) * DD + c4);
        float4 b = *(const float4*)(Q + (size_t)(bj + row) * DD + c4);
        __half2 a01 = __floats2half2_rn(a.x, a.y), a23 = __floats2half2_rn(a.z, a.w);
        __half2 b01 = __floats2half2_rn(b.x, b.y), b23 = __floats2half2_rn(b.z, b.w);
        uint2 pa; pa.x = *(uint32_t*)&a01; pa.y = *(uint32_t*)&a23;
        uint2 pb; pb.x = *(uint32_t*)&b01; pb.y = *(uint32_t*)&b23;
        *(uint2*)(Ps + row * LDSW + c4) = pa;
        *(uint2*)(Qs + row * LDSW + c4) = pb;
    }
    if (tid < 128) {
        s_pn[tid] = g_pn[bi + tid];
        s_qn[tid] = g_qn[bj + tid];
    }
    __syncthreads();

    float acc[2][8][4];
    #pragma unroll
    for (int i = 0; i < 2; ++i)
        #pragma unroll
        for (int j = 0; j < 8; ++j)
            #pragma unroll
            for (int r = 0; r < 4; ++r) acc[i][j][r] = 0.f;

    #pragma unroll
    for (int ks = 0; ks < 4; ++ks) {
        const int k0 = ks * 16;
        uint32_t A[2][4], B[8][2];
        #pragma unroll
        for (int i = 0; i < 2; ++i) {
            const __half* base = Ps + (mrow + i * 16 + g) * LDSW + k0 + tq * 2;
            A[i][0] = *(const uint32_t*)(base);
            A[i][1] = *(const uint32_t*)(base + 8 * LDSW);
            A[i][2] = *(const uint32_t*)(base + 8);
            A[i][3] = *(const uint32_t*)(base + 8 * LDSW + 8);
        }
        #pragma unroll
        for (int j = 0; j < 8; ++j) {
            const __half* base = Qs + (ncol + j * 8 + g) * LDSW + k0 + tq * 2;
            B[j][0] = *(const uint32_t*)(base);
            B[j][1] = *(const uint32_t*)(base + 8);
        }
        #pragma unroll
        for (int i = 0; i < 2; ++i)
            #pragma unroll
            for (int j = 0; j < 8; ++j)
                asm volatile(
                    "mma.sync.aligned.m16n8k16.row.col.f32.f16.f16.f32 "
                    "{%0,%1,%2,%3}, {%4,%5,%6,%7}, {%8,%9}, {%0,%1,%2,%3};"
                    : "+f"(acc[i][j][0]), "+f"(acc[i][j][1]),
                      "+f"(acc[i][j][2]), "+f"(acc[i][j][3])
                    : "r"(A[i][0]), "r"(A[i][1]), "r"(A[i][2]), "r"(A[i][3]),
                      "r"(B[j][0]), "r"(B[j][1]));
    }

    #pragma unroll
    for (int i = 0; i < 2; ++i) {
        const int r0 = mrow + i * 16 + g;
        const float pn0 = s_pn[r0], pn1 = s_pn[r0 + 8];
        #pragma unroll
        for (int j = 0; j < 8; ++j) {
            const int c = ncol + j * 8 + tq * 2;
            const float qn0 = s_qn[c], qn1 = s_qn[c + 1];
            float s00 = fmaxf(pn0 + qn0 - 2.0f * acc[i][j][0], 0.f);
            float s01 = fmaxf(pn0 + qn1 - 2.0f * acc[i][j][1], 0.f);
            float s10 = fmaxf(pn1 + qn0 - 2.0f * acc[i][j][2], 0.f);
            float s11 = fmaxf(pn1 + qn1 - 2.0f * acc[i][j][3], 0.f);
            const float m = -14.4269504f;   // -log2(e)/eps
            float k00 = fex2(fsqrt_ap(s00) * m + KSH);
            float k01 = fex2(fsqrt_ap(s01) * m + KSH);
            float k10 = fex2(fsqrt_ap(s10) * m + KSH);
            float k11 = fex2(fsqrt_ap(s11) * m + KSH);
            *(uint16_t*)(g_K + (size_t)(bi + r0)     * NN + bj + c) = enc2(k00, k01);
            *(uint16_t*)(g_K + (size_t)(bi + r0 + 8) * NN + bj + c) = enc2(k10, k11);
        }
    }
}

// One Sinkhorn half-step, warp-per-row: y_row = 2^KSH / sum_j K'_rj * x_j.
__global__ __launch_bounds__(256) void sink_kernel(int phase) {
    const float* __restrict__ x = phase ? g_v : g_u;
    float* __restrict__       y = phase ? g_u : g_v;
    const int row  = (blockIdx.x << 3) + (threadIdx.x >> 5);
    const int lane = threadIdx.x & 31;
    const uint4*  __restrict__ K16 = (const uint4*)(g_K + (size_t)row * NN);
    const float4* __restrict__ x4  = (const float4*)x;
    float s = 0.f;
    #pragma unroll 4
    for (int i = lane; i < NN / 16; i += 32) {
        uint4 k = K16[i];
        float2 a0 = dec2(k.x), a1 = dec2(k.x >> 16);
        float2 b0 = dec2(k.y), b1 = dec2(k.y >> 16);
        float2 c0 = dec2(k.z), c1 = dec2(k.z >> 16);
        float2 d0 = dec2(k.w), d1 = dec2(k.w >> 16);
        float4 x0 = x4[4 * i], x1 = x4[4 * i + 1];
        float4 x2 = x4[4 * i + 2], x3 = x4[4 * i + 3];
        s += a0.x * x0.x + a0.y * x0.y + a1.x * x0.z + a1.y * x0.w
           + b0.x * x1.x + b0.y * x1.y + b1.x * x1.z + b1.y * x1.w
           + c0.x * x2.x + c0.y * x2.y + c1.x * x2.z + c1.y * x2.w
           + d0.x * x3.x + d0.y * x3.y + d1.x * x3.z + d1.y * x3.w;
    }
    #pragma unroll
    for (int o = 16; o; o >>= 1) s += __shfl_down_sync(0xFFFFFFFFu, s, o);
    if (lane == 0) y[row] = 1024.0f / s;   // 2^KSH
}

// Fused final half-step + loss:
//   s1 = sum_j K'_rj v_j,  s2 = sum_j K'_rj v_j * C_rj,  C = -eps*ln2*(lg2 K' - KSH)
//   loss += s2 / s1   (the 2^KSH scale cancels)
__global__ __launch_bounds__(256) void fused_loss_kernel() {
    const int row  = (blockIdx.x << 3) + (threadIdx.x >> 5);
    const int lane = threadIdx.x & 31;
    const int wid  = threadIdx.x >> 5;
    const uint4*  __restrict__ K16 = (const uint4*)(g_K + (size_t)row * NN);
    const float4* __restrict__ v4  = (const float4*)g_v;
    float s1 = 0.f, s2 = 0.f;
    const float m2 = -0.069314718f;   // -eps * ln2
    #pragma unroll 2
    for (int i = lane; i < NN / 16; i += 32) {
        uint4 k = K16[i];
        float2 f[8];
        f[0] = dec2(k.x); f[1] = dec2(k.x >> 16);
        f[2] = dec2(k.y); f[3] = dec2(k.y >> 16);
        f[4] = dec2(k.z); f[5] = dec2(k.z >> 16);
        f[6] = dec2(k.w); f[7] = dec2(k.w >> 16);
        float4 xv[4];
        xv[0] = v4[4 * i];     xv[1] = v4[4 * i + 1];
        xv[2] = v4[4 * i + 2]; xv[3] = v4[4 * i + 3];
        const float* xs = (const float*)xv;
        #pragma unroll
        for (int q = 0; q < 8; ++q) {
            float tx = f[q].x * xs[2 * q];
            float ty = f[q].y * xs[2 * q + 1];
            s1 += tx + ty;
            s2 += tx * (m2 * (flg2(f[q].x) - KSH))
                + ty * (m2 * (flg2(f[q].y) - KSH));
        }
    }
    #pragma unroll
    for (int o = 16; o; o >>= 1) {
        s1 += __shfl_down_sync(0xFFFFFFFFu, s1, o);
        s2 += __shfl_down_sync(0xFFFFFFFFu, s2, o);
    }
    __shared__ double sh[8];
    if (lane == 0) sh[wid] = (double)(s2 / s1);
    __syncthreads();
    if (threadIdx.x == 0) {
        double t = sh[0] + sh[1] + sh[2] + sh[3] + sh[4] + sh[5] + sh[6] + sh[7];
        atomicAdd(&g_loss, t);
    }
}

__global__ void out_kernel(float* out) {
    if (threadIdx.x == 0) out[0] = (float)g_loss;
}

extern "C" void kernel_launch(void* const* d_in, const int* in_sizes, int n_in,
                              void* d_out, int out_size) {
    const float* P = (const float*)d_in[0];
    const float* Q = (const float*)d_in[1];
    prep_kernel<<<(NN + 255) / 256, 256>>>(P, Q);
    ck_kernel<<<dim3(NN / 128, NN / 128), 256>>>(P, Q);
    for (int it = 0; it < 4; ++it) {
        sink_kernel<<<NN / 8, 256>>>(0);
        sink_kernel<<<NN / 8, 256>>>(1);
    }
    sink_kernel<<<NN / 8, 256>>>(0);      // v of iteration 5
    fused_loss_kernel<<<NN / 8, 256>>>(); // final u half-step fused with loss
    out_kernel<<<1, 1>>>((float*)d_out);
}

// round 10
// speedup vs baseline: 1.3921x; 1.3921x over previous
#include <cuda_runtime.h>
#include <cuda_fp16.h>
#include <cstdint>

#define NN 8192
#define DD 64

static __device__ __half g_K[(size_t)NN * NN];   // 128 MB: K = exp(-C/eps), fp16
static __device__ float  g_u[NN];
static __device__ float  g_v[NN];
static __device__ float  g_pn[NN];
static __device__ float  g_qn[NN];
static __device__ float  g_rsum[NN];
static __device__ double g_loss;

__device__ __forceinline__ float fsqrt_ap(float x) { float r; asm("sqrt.approx.f32 %0, %1;" : "=f"(r) : "f"(x)); return r; }
__device__ __forceinline__ float fex2(float x)     { float r; asm("ex2.approx.f32 %0, %1;"  : "=f"(r) : "f"(x)); return r; }
__device__ __forceinline__ float flg2(float x)     { float r; asm("lg2.approx.f32 %0, %1;"  : "=f"(r) : "f"(x)); return r; }

__global__ void prep_kernel(const float* __restrict__ P, const float* __restrict__ Q) {
    int i = blockIdx.x * blockDim.x + threadIdx.x;
    if (i == 0) g_loss = 0.0;
    if (i < NN) {
        const float4* p = (const float4*)(P + (size_t)i * DD);
        const float4* q = (const float4*)(Q + (size_t)i * DD);
        float sp = 0.f, sq = 0.f;
        #pragma unroll
        for (int k = 0; k < DD / 4; ++k) {
            float4 a = p[k]; sp += a.x*a.x + a.y*a.y + a.z*a.z + a.w*a.w;
            float4 b = q[k]; sq += b.x*b.x + b.y*b.y + b.z*b.z + b.w*b.w;
        }
        g_pn[i] = sp;
        g_qn[i] = sq;
        g_rsum[i] = 0.0f;
    }
}

// K[i][j] = exp(-sqrt(max(pn_i+qn_j-2 P_i.Q_j,0))/eps) via mma.sync m16n8k16,
// fp16 store, and fused row-sum accumulation (for v1 = 64/rowsum).
#define LDSW 72
__global__ __launch_bounds__(256) void ck_kernel(const float* __restrict__ P,
                                                 const float* __restrict__ Q) {
    __shared__ __half Ps[128 * LDSW];
    __shared__ __half Qs[128 * LDSW];
    __shared__ float  s_pn[128], s_qn[128], s_rsum[128];

    const int bi = blockIdx.y * 128, bj = blockIdx.x * 128;
    const int tid = threadIdx.x;
    const int wid = tid >> 5, lane = tid & 31;
    const int g = lane >> 2, tq = lane & 3;
    const int mrow = (wid >> 1) * 32, ncol = (wid & 1) * 64;

    #pragma unroll
    for (int r = 0; r < 8; ++r) {
        int idx = tid + r * 256;
        int row = idx >> 4;
        int c4  = (idx & 15) << 2;
        float4 a = *(const float4*)(P + (size_t)(bi + row) * DD + c4);
        float4 b = *(const float4*)(Q + (size_t)(bj + row) * DD + c4);
        __half2 a01 = __floats2half2_rn(a.x, a.y), a23 = __floats2half2_rn(a.z, a.w);
        __half2 b01 = __floats2half2_rn(b.x, b.y), b23 = __floats2half2_rn(b.z, b.w);
        uint2 pa; pa.x = *(uint32_t*)&a01; pa.y = *(uint32_t*)&a23;
        uint2 pb; pb.x = *(uint32_t*)&b01; pb.y = *(uint32_t*)&b23;
        *(uint2*)(Ps + row * LDSW + c4) = pa;
        *(uint2*)(Qs + row * LDSW + c4) = pb;
    }
    if (tid < 128) {
        s_pn[tid] = g_pn[bi + tid];
        s_qn[tid] = g_qn[bj + tid];
        s_rsum[tid] = 0.0f;
    }
    __syncthreads();

    float acc[2][8][4];
    #pragma unroll
    for (int i = 0; i < 2; ++i)
        #pragma unroll
        for (int j = 0; j < 8; ++j)
            #pragma unroll
            for (int r = 0; r < 4; ++r) acc[i][j][r] = 0.f;

    #pragma unroll
    for (int ks = 0; ks < 4; ++ks) {
        const int k0 = ks * 16;
        uint32_t A[2][4], B[8][2];
        #pragma unroll
        for (int i = 0; i < 2; ++i) {
            const __half* base = Ps + (mrow + i * 16 + g) * LDSW + k0 + tq * 2;
            A[i][0] = *(const uint32_t*)(base);
            A[i][1] = *(const uint32_t*)(base + 8 * LDSW);
            A[i][2] = *(const uint32_t*)(base + 8);
            A[i][3] = *(const uint32_t*)(base + 8 * LDSW + 8);
        }
        #pragma unroll
        for (int j = 0; j < 8; ++j) {
            const __half* base = Qs + (ncol + j * 8 + g) * LDSW + k0 + tq * 2;
            B[j][0] = *(const uint32_t*)(base);
            B[j][1] = *(const uint32_t*)(base + 8);
        }
        #pragma unroll
        for (int i = 0; i < 2; ++i)
            #pragma unroll
            for (int j = 0; j < 8; ++j)
                asm volatile(
                    "mma.sync.aligned.m16n8k16.row.col.f32.f16.f16.f32 "
                    "{%0,%1,%2,%3}, {%4,%5,%6,%7}, {%8,%9}, {%0,%1,%2,%3};"
                    : "+f"(acc[i][j][0]), "+f"(acc[i][j][1]),
                      "+f"(acc[i][j][2]), "+f"(acc[i][j][3])
                    : "r"(A[i][0]), "r"(A[i][1]), "r"(A[i][2]), "r"(A[i][3]),
                      "r"(B[j][0]), "r"(B[j][1]));
    }

    #pragma unroll
    for (int i = 0; i < 2; ++i) {
        const int r0 = mrow + i * 16 + g;
        const float pn0 = s_pn[r0], pn1 = s_pn[r0 + 8];
        float rs0 = 0.f, rs1 = 0.f;
        #pragma unroll
        for (int j = 0; j < 8; ++j) {
            const int c = ncol + j * 8 + tq * 2;
            const float qn0 = s_qn[c], qn1 = s_qn[c + 1];
            float s00 = fmaxf(pn0 + qn0 - 2.0f * acc[i][j][0], 0.f);
            float s01 = fmaxf(pn0 + qn1 - 2.0f * acc[i][j][1], 0.f);
            float s10 = fmaxf(pn1 + qn0 - 2.0f * acc[i][j][2], 0.f);
            float s11 = fmaxf(pn1 + qn1 - 2.0f * acc[i][j][3], 0.f);
            const float m = -14.4269504f;   // -log2(e)/eps
            float k00 = fex2(fsqrt_ap(s00) * m), k01 = fex2(fsqrt_ap(s01) * m);
            float k10 = fex2(fsqrt_ap(s10) * m), k11 = fex2(fsqrt_ap(s11) * m);
            rs0 += k00 + k01;
            rs1 += k10 + k11;
            __half2 h0 = __floats2half2_rn(k00, k01);
            __half2 h1 = __floats2half2_rn(k10, k11);
            *(uint32_t*)(g_K + (size_t)(bi + r0)     * NN + bj + c) = *(uint32_t*)&h0;
            *(uint32_t*)(g_K + (size_t)(bi + r0 + 8) * NN + bj + c) = *(uint32_t*)&h1;
        }
        // reduce across the 4 quad lanes (tq), then one smem atomic per row
        rs0 += __shfl_xor_sync(0xFFFFFFFFu, rs0, 1);
        rs0 += __shfl_xor_sync(0xFFFFFFFFu, rs0, 2);
        rs1 += __shfl_xor_sync(0xFFFFFFFFu, rs1, 1);
        rs1 += __shfl_xor_sync(0xFFFFFFFFu, rs1, 2);
        if (tq == 0) {
            atomicAdd(&s_rsum[r0],     rs0);
            atomicAdd(&s_rsum[r0 + 8], rs1);
        }
    }
    __syncthreads();
    if (tid < 128) atomicAdd(&g_rsum[bi + tid], s_rsum[tid]);
}

// v1 = 64 / rowsum   (first Sinkhorn half-step, free)
__global__ void rsum_to_v_kernel() {
    int i = blockIdx.x * blockDim.x + threadIdx.x;
    if (i < NN) g_v[i] = 64.0f / g_rsum[i];
}

// One Sinkhorn half-step, 2 rows per warp: y_r = 1 / sum_j K_rj x_j.
// phase 0: x=u -> y=v ; phase 1: x=v -> y=u.
__global__ __launch_bounds__(256) void sink_kernel(int phase) {
    const float* __restrict__ x = phase ? g_v : g_u;
    float* __restrict__       y = phase ? g_u : g_v;
    const int w    = (blockIdx.x << 3) + (threadIdx.x >> 5);
    const int lane = threadIdx.x & 31;
    const int ra = w, rb = w + NN / 2;
    const uint4*  __restrict__ Ka = (const uint4*)(g_K + (size_t)ra * NN);
    const uint4*  __restrict__ Kb = (const uint4*)(g_K + (size_t)rb * NN);
    const float4* __restrict__ x4 = (const float4*)x;
    float sa = 0.f, sb = 0.f;
    #pragma unroll 4
    for (int i = lane; i < NN / 8; i += 32) {
        uint4 ka = Ka[i], kb = Kb[i];
        float4 x0 = x4[2 * i], x1 = x4[2 * i + 1];
        float2 a0 = __half22float2(*(__half2*)&ka.x);
        float2 a1 = __half22float2(*(__half2*)&ka.y);
        float2 a2 = __half22float2(*(__half2*)&ka.z);
        float2 a3 = __half22float2(*(__half2*)&ka.w);
        float2 b0 = __half22float2(*(__half2*)&kb.x);
        float2 b1 = __half22float2(*(__half2*)&kb.y);
        float2 b2 = __half22float2(*(__half2*)&kb.z);
        float2 b3 = __half22float2(*(__half2*)&kb.w);
        sa += a0.x * x0.x + a0.y * x0.y + a1.x * x0.z + a1.y * x0.w
            + a2.x * x1.x + a2.y * x1.y + a3.x * x1.z + a3.y * x1.w;
        sb += b0.x * x0.x + b0.y * x0.y + b1.x * x0.z + b1.y * x0.w
            + b2.x * x1.x + b2.y * x1.y + b3.x * x1.z + b3.y * x1.w;
    }
    #pragma unroll
    for (int o = 16; o; o >>= 1) {
        sa += __shfl_down_sync(0xFFFFFFFFu, sa, o);
        sb += __shfl_down_sync(0xFFFFFFFFu, sb, o);
    }
    if (lane == 0) {
        y[ra] = 1.0f / sa;
        y[rb] = 1.0f / sb;
    }
}

// Fused final half-step + loss, 2 rows per warp:
//   s1 = sum_j K_rj v_j ; s2 = sum_j K_rj v_j C_rj (C = -eps ln K); loss += s2/s1
__global__ __launch_bounds__(256) void fused_loss_kernel() {
    const int w    = (blockIdx.x << 3) + (threadIdx.x >> 5);
    const int lane = threadIdx.x & 31;
    const int wid  = threadIdx.x >> 5;
    const int ra = w, rb = w + NN / 2;
    const uint4*  __restrict__ Ka = (const uint4*)(g_K + (size_t)ra * NN);
    const uint4*  __restrict__ Kb = (const uint4*)(g_K + (size_t)rb * NN);
    const float4* __restrict__ v4 = (const float4*)g_v;
    float s1a = 0.f, s2a = 0.f, s1b = 0.f, s2b = 0.f;
    const float m = -0.069314718f;   // -eps * ln2
    #pragma unroll 2
    for (int i = lane; i < NN / 8; i += 32) {
        uint4 ka = Ka[i], kb = Kb[i];
        float4 x0 = v4[2 * i], x1 = v4[2 * i + 1];
        float2 fa[4], fb[4];
        fa[0] = __half22float2(*(__half2*)&ka.x);
        fa[1] = __half22float2(*(__half2*)&ka.y);
        fa[2] = __half22float2(*(__half2*)&ka.z);
        fa[3] = __half22float2(*(__half2*)&ka.w);
        fb[0] = __half22float2(*(__half2*)&kb.x);
        fb[1] = __half22float2(*(__half2*)&kb.y);
        fb[2] = __half22float2(*(__half2*)&kb.z);
        fb[3] = __half22float2(*(__half2*)&kb.w);
        const float* xs = (const float*)&x0;   // x0,x1 contiguous? not guaranteed; use explicit
        float xv[8] = {x0.x, x0.y, x0.z, x0.w, x1.x, x1.y, x1.z, x1.w};
        #pragma unroll
        for (int q = 0; q < 4; ++q) {
            float ta0 = fa[q].x * xv[2 * q], ta1 = fa[q].y * xv[2 * q + 1];
            float tb0 = fb[q].x * xv[2 * q], tb1 = fb[q].y * xv[2 * q + 1];
            s1a += ta0 + ta1;
            s1b += tb0 + tb1;
            s2a += ta0 * (m * flg2(fa[q].x)) + ta1 * (m * flg2(fa[q].y));
            s2b += tb0 * (m * flg2(fb[q].x)) + tb1 * (m * flg2(fb[q].y));
        }
        (void)xs;
    }
    #pragma unroll
    for (int o = 16; o; o >>= 1) {
        s1a += __shfl_down_sync(0xFFFFFFFFu, s1a, o);
        s2a += __shfl_down_sync(0xFFFFFFFFu, s2a, o);
        s1b += __shfl_down_sync(0xFFFFFFFFu, s1b, o);
        s2b += __shfl_down_sync(0xFFFFFFFFu, s2b, o);
    }
    __shared__ double sh[8];
    if (lane == 0) sh[wid] = (double)(s2a / s1a) + (double)(s2b / s1b);
    __syncthreads();
    if (threadIdx.x == 0) {
        double t = sh[0] + sh[1] + sh[2] + sh[3] + sh[4] + sh[5] + sh[6] + sh[7];
        atomicAdd(&g_loss, t);
    }
}

__global__ void out_kernel(float* out) {
    if (threadIdx.x == 0) out[0] = (float)g_loss;
}

extern "C" void kernel_launch(void* const* d_in, const int* in_sizes, int n_in,
                              void* d_out, int out_size) {
    const float* P = (const float*)d_in[0];
    const float* Q = (const float*)d_in[1];
    prep_kernel<<<(NN + 255) / 256, 256>>>(P, Q);
    ck_kernel<<<dim3(NN / 128, NN / 128), 256>>>(P, Q);           // writes K, rowsums
    rsum_to_v_kernel<<<(NN + 255) / 256, 256>>>();                // v1 = 64/rowsum
    for (int it = 0; it < 4; ++it) {
        sink_kernel<<<NN / 16, 256>>>(1);   // u_{it+1} = 1/(K v)
        sink_kernel<<<NN / 16, 256>>>(0);   // v_{it+2} = 1/(K u)
    }
    fused_loss_kernel<<<NN / 16, 256>>>();  // u5 + loss fused
    out_kernel<<<1, 1>>>((float*)d_out);
}

// round 11
// speedup vs baseline: 1.6078x; 1.1549x over previous
#include <cuda_runtime.h>
#include <cuda_fp16.h>
#include <cstdint>

#define NN 8192
#define DD 64

static __device__ __half g_K[(size_t)NN * NN];   // 128 MB: K = exp(-C/eps), fp16
static __device__ float  g_u[NN];
static __device__ float  g_v[NN];
static __device__ float  g_pn[NN];
static __device__ float  g_qn[NN];
static __device__ float  g_rsum[NN];
static __device__ double g_loss;

__device__ __forceinline__ float fsqrt_ap(float x) { float r; asm("sqrt.approx.f32 %0, %1;" : "=f"(r) : "f"(x)); return r; }
__device__ __forceinline__ float fex2(float x)     { float r; asm("ex2.approx.f32 %0, %1;"  : "=f"(r) : "f"(x)); return r; }
__device__ __forceinline__ float flg2(float x)     { float r; asm("lg2.approx.f32 %0, %1;"  : "=f"(r) : "f"(x)); return r; }

__global__ void prep_kernel(const float* __restrict__ P, const float* __restrict__ Q) {
    int i = blockIdx.x * blockDim.x + threadIdx.x;
    if (i == 0) g_loss = 0.0;
    if (i < NN) {
        const float4* p = (const float4*)(P + (size_t)i * DD);
        const float4* q = (const float4*)(Q + (size_t)i * DD);
        float sp = 0.f, sq = 0.f;
        #pragma unroll
        for (int k = 0; k < DD / 4; ++k) {
            float4 a = p[k]; sp += a.x*a.x + a.y*a.y + a.z*a.z + a.w*a.w;
            float4 b = q[k]; sq += b.x*b.x + b.y*b.y + b.z*b.z + b.w*b.w;
        }
        g_pn[i] = sp;
        g_qn[i] = sq;
        g_rsum[i] = 0.0f;
    }
}

// K[i][j] = exp(-sqrt(max(pn_i+qn_j-2 P_i.Q_j,0))/eps) via mma.sync m16n8k16,
// fp16 store, fused row-sum accumulation (first Sinkhorn half-step for free).
#define LDSW 72
__global__ __launch_bounds__(256) void ck_kernel(const float* __restrict__ P,
                                                 const float* __restrict__ Q) {
    __shared__ __half Ps[128 * LDSW];
    __shared__ __half Qs[128 * LDSW];
    __shared__ float  s_pn[128], s_qn[128], s_rsum[128];

    const int bi = blockIdx.y * 128, bj = blockIdx.x * 128;
    const int tid = threadIdx.x;
    const int wid = tid >> 5, lane = tid & 31;
    const int g = lane >> 2, tq = lane & 3;
    const int mrow = (wid >> 1) * 32, ncol = (wid & 1) * 64;

    #pragma unroll
    for (int r = 0; r < 8; ++r) {
        int idx = tid + r * 256;
        int row = idx >> 4;
        int c4  = (idx & 15) << 2;
        float4 a = *(const float4*)(P + (size_t)(bi + row) * DD + c4);
        float4 b = *(const float4*)(Q + (size_t)(bj + row) * DD + c4);
        __half2 a01 = __floats2half2_rn(a.x, a.y), a23 = __floats2half2_rn(a.z, a.w);
        __half2 b01 = __floats2half2_rn(b.x, b.y), b23 = __floats2half2_rn(b.z, b.w);
        uint2 pa; pa.x = *(uint32_t*)&a01; pa.y = *(uint32_t*)&a23;
        uint2 pb; pb.x = *(uint32_t*)&b01; pb.y = *(uint32_t*)&b23;
        *(uint2*)(Ps + row * LDSW + c4) = pa;
        *(uint2*)(Qs + row * LDSW + c4) = pb;
    }
    if (tid < 128) {
        s_pn[tid] = g_pn[bi + tid];
        s_qn[tid] = g_qn[bj + tid];
        s_rsum[tid] = 0.0f;
    }
    __syncthreads();

    float acc[2][8][4];
    #pragma unroll
    for (int i = 0; i < 2; ++i)
        #pragma unroll
        for (int j = 0; j < 8; ++j)
            #pragma unroll
            for (int r = 0; r < 4; ++r) acc[i][j][r] = 0.f;

    #pragma unroll
    for (int ks = 0; ks < 4; ++ks) {
        const int k0 = ks * 16;
        uint32_t A[2][4], B[8][2];
        #pragma unroll
        for (int i = 0; i < 2; ++i) {
            const __half* base = Ps + (mrow + i * 16 + g) * LDSW + k0 + tq * 2;
            A[i][0] = *(const uint32_t*)(base);
            A[i][1] = *(const uint32_t*)(base + 8 * LDSW);
            A[i][2] = *(const uint32_t*)(base + 8);
            A[i][3] = *(const uint32_t*)(base + 8 * LDSW + 8);
        }
        #pragma unroll
        for (int j = 0; j < 8; ++j) {
            const __half* base = Qs + (ncol + j * 8 + g) * LDSW + k0 + tq * 2;
            B[j][0] = *(const uint32_t*)(base);
            B[j][1] = *(const uint32_t*)(base + 8);
        }
        #pragma unroll
        for (int i = 0; i < 2; ++i)
            #pragma unroll
            for (int j = 0; j < 8; ++j)
                asm volatile(
                    "mma.sync.aligned.m16n8k16.row.col.f32.f16.f16.f32 "
                    "{%0,%1,%2,%3}, {%4,%5,%6,%7}, {%8,%9}, {%0,%1,%2,%3};"
                    : "+f"(acc[i][j][0]), "+f"(acc[i][j][1]),
                      "+f"(acc[i][j][2]), "+f"(acc[i][j][3])
                    : "r"(A[i][0]), "r"(A[i][1]), "r"(A[i][2]), "r"(A[i][3]),
                      "r"(B[j][0]), "r"(B[j][1]));
    }

    #pragma unroll
    for (int i = 0; i < 2; ++i) {
        const int r0 = mrow + i * 16 + g;
        const float pn0 = s_pn[r0], pn1 = s_pn[r0 + 8];
        float rs0 = 0.f, rs1 = 0.f;
        #pragma unroll
        for (int j = 0; j < 8; ++j) {
            const int c = ncol + j * 8 + tq * 2;
            const float qn0 = s_qn[c], qn1 = s_qn[c + 1];
            float s00 = fmaxf(pn0 + qn0 - 2.0f * acc[i][j][0], 0.f);
            float s01 = fmaxf(pn0 + qn1 - 2.0f * acc[i][j][1], 0.f);
            float s10 = fmaxf(pn1 + qn0 - 2.0f * acc[i][j][2], 0.f);
            float s11 = fmaxf(pn1 + qn1 - 2.0f * acc[i][j][3], 0.f);
            const float m = -14.4269504f;   // -log2(e)/eps
            float k00 = fex2(fsqrt_ap(s00) * m), k01 = fex2(fsqrt_ap(s01) * m);
            float k10 = fex2(fsqrt_ap(s10) * m), k11 = fex2(fsqrt_ap(s11) * m);
            rs0 += k00 + k01;
            rs1 += k10 + k11;
            __half2 h0 = __floats2half2_rn(k00, k01);
            __half2 h1 = __floats2half2_rn(k10, k11);
            *(uint32_t*)(g_K + (size_t)(bi + r0)     * NN + bj + c) = *(uint32_t*)&h0;
            *(uint32_t*)(g_K + (size_t)(bi + r0 + 8) * NN + bj + c) = *(uint32_t*)&h1;
        }
        rs0 += __shfl_xor_sync(0xFFFFFFFFu, rs0, 1);
        rs0 += __shfl_xor_sync(0xFFFFFFFFu, rs0, 2);
        rs1 += __shfl_xor_sync(0xFFFFFFFFu, rs1, 1);
        rs1 += __shfl_xor_sync(0xFFFFFFFFu, rs1, 2);
        if (tq == 0) {
            atomicAdd(&s_rsum[r0],     rs0);
            atomicAdd(&s_rsum[r0 + 8], rs1);
        }
    }
    __syncthreads();
    if (tid < 128) atomicAdd(&g_rsum[bi + tid], s_rsum[tid]);
}

// v1 = 64 / rowsum   (first Sinkhorn half-step, free)
__global__ void rsum_to_v_kernel() {
    int i = blockIdx.x * blockDim.x + threadIdx.x;
    if (i < NN) g_v[i] = 64.0f / g_rsum[i];
}

// One Sinkhorn half-step, warp-per-row (grid 1024 x 8 warps), streaming loads.
__global__ __launch_bounds__(256) void sink_kernel(int phase) {
    const float* __restrict__ x = phase ? g_v : g_u;
    float* __restrict__       y = phase ? g_u : g_v;
    const int row  = (blockIdx.x << 3) + (threadIdx.x >> 5);
    const int lane = threadIdx.x & 31;
    const uint4*  __restrict__ K8 = (const uint4*)(g_K + (size_t)row * NN);
    const float4* __restrict__ x4 = (const float4*)x;
    float s = 0.f;
    #pragma unroll 4
    for (int i = lane; i < NN / 8; i += 32) {
        uint4 k = __ldcs(&K8[i]);
        float2 f0 = __half22float2(*(__half2*)&k.x);
        float2 f1 = __half22float2(*(__half2*)&k.y);
        float2 f2 = __half22float2(*(__half2*)&k.z);
        float2 f3 = __half22float2(*(__half2*)&k.w);
        float4 xa = x4[2 * i], xb = x4[2 * i + 1];
        s += f0.x * xa.x + f0.y * xa.y + f1.x * xa.z + f1.y * xa.w
           + f2.x * xb.x + f2.y * xb.y + f3.x * xb.z + f3.y * xb.w;
    }
    #pragma unroll
    for (int o = 16; o; o >>= 1) s += __shfl_down_sync(0xFFFFFFFFu, s, o);
    if (lane == 0) y[row] = 1.0f / s;
}

// Fused final half-step + loss, warp-per-row:
//   s1 = sum_j K_rj v_j ; s2 = sum_j K_rj v_j C_rj (C = -eps ln K); loss += s2/s1
__global__ __launch_bounds__(256) void fused_loss_kernel() {
    const int row  = (blockIdx.x << 3) + (threadIdx.x >> 5);
    const int lane = threadIdx.x & 31;
    const int wid  = threadIdx.x >> 5;
    const uint4*  __restrict__ K8 = (const uint4*)(g_K + (size_t)row * NN);
    const float4* __restrict__ v4 = (const float4*)g_v;
    float s1 = 0.f, s2 = 0.f;
    const float m = -0.069314718f;   // -eps * ln2
    #pragma unroll 2
    for (int i = lane; i < NN / 8; i += 32) {
        uint4 k = __ldcs(&K8[i]);
        float2 f0 = __half22float2(*(__half2*)&k.x);
        float2 f1 = __half22float2(*(__half2*)&k.y);
        float2 f2 = __half22float2(*(__half2*)&k.z);
        float2 f3 = __half22float2(*(__half2*)&k.w);
        float4 va = v4[2 * i], vb = v4[2 * i + 1];
        float t0 = f0.x * va.x, t1 = f0.y * va.y, t2 = f1.x * va.z, t3 = f1.y * va.w;
        float t4 = f2.x * vb.x, t5 = f2.y * vb.y, t6 = f3.x * vb.z, t7 = f3.y * vb.w;
        s1 += t0 + t1 + t2 + t3 + t4 + t5 + t6 + t7;
        s2 += t0 * (m * flg2(f0.x)) + t1 * (m * flg2(f0.y))
            + t2 * (m * flg2(f1.x)) + t3 * (m * flg2(f1.y))
            + t4 * (m * flg2(f2.x)) + t5 * (m * flg2(f2.y))
            + t6 * (m * flg2(f3.x)) + t7 * (m * flg2(f3.y));
    }
    #pragma unroll
    for (int o = 16; o; o >>= 1) {
        s1 += __shfl_down_sync(0xFFFFFFFFu, s1, o);
        s2 += __shfl_down_sync(0xFFFFFFFFu, s2, o);
    }
    __shared__ double sh[8];
    if (lane == 0) sh[wid] = (double)(s2 / s1);
    __syncthreads();
    if (threadIdx.x == 0) {
        double t = sh[0] + sh[1] + sh[2] + sh[3] + sh[4] + sh[5] + sh[6] + sh[7];
        atomicAdd(&g_loss, t);
    }
}

__global__ void out_kernel(float* out) {
    if (threadIdx.x == 0) out[0] = (float)g_loss;
}

extern "C" void kernel_launch(void* const* d_in, const int* in_sizes, int n_in,
                              void* d_out, int out_size) {
    const float* P = (const float*)d_in[0];
    const float* Q = (const float*)d_in[1];
    prep_kernel<<<(NN + 255) / 256, 256>>>(P, Q);
    ck_kernel<<<dim3(NN / 128, NN / 128), 256>>>(P, Q);   // writes K, rowsums
    rsum_to_v_kernel<<<(NN + 255) / 256, 256>>>();        // v1 = 64/rowsum
    for (int it = 0; it < 4; ++it) {
        sink_kernel<<<NN / 8, 256>>>(1);   // u = 1/(K v)
        sink_kernel<<<NN / 8, 256>>>(0);   // v = 1/(K u)
    }
    fused_loss_kernel<<<NN / 8, 256>>>();  // final u half-step fused with loss
    out_kernel<<<1, 1>>>((float*)d_out);
}